// round 10
// baseline (speedup 1.0000x reference)
#include <cuda_runtime.h>
#include <cuda_fp16.h>
#include <cstdint>

// Problem constants
#define B_   8
#define N_   2048
#define F0_  128
#define HID_ 64
#define OUT_ 16
#define K_   10

#define VCHUNKS 32                  // 64 rows per chunk
#define RPC     64                  // rows per chunk
#define GRID    256                 // 8 wtiles x 32 vchunks
#define TPB     256

// ---------------- device scratch (static; no allocation) ----------------
__device__ float g_zvec[2][N_];              // persisted z_{j-1} ping-pong
__device__ float g_pz[2][VCHUNKS][N_];       // double-buffered partials of L^T z
__device__ float g_pr[2][VCHUNKS][N_];       // double-buffered partials of L^T r
__device__ float g_part[B_][32][HID_];       // per-(b,chunk) partial Hg sums
__device__ unsigned g_barcnt = 0;            // monotonic ticket counter
__device__ unsigned g_barrel = 0;            // monotonic release generation

__constant__ float c_binom[K_ + 1] = {1.f, 10.f, 45.f, 120.f, 210.f, 252.f,
                                      210.f, 120.f, 45.f, 10.f, 1.f};

// Grid barrier: monotonic counters stay consistent across graph replays.
__device__ __forceinline__ void grid_arrive_wait() {
    __threadfence();
    unsigned ticket = atomicAdd(&g_barcnt, 1u) + 1u;
    unsigned gen = (ticket + GRID - 1u) / GRID;
    if ((ticket & (GRID - 1u)) == 0u) {
        atomicAdd(&g_barrel, 1u);
    }
    int spins = 0;
    while (*((volatile unsigned*)&g_barrel) < gen) {
        if (++spins > 64) __nanosleep(32);
    }
    __threadfence();
}

__device__ __forceinline__ void gsync(int tid) {
    __syncthreads();
    if (tid == 0) grid_arrive_wait();
    __syncthreads();
}

__global__ __launch_bounds__(TPB) void mega_kernel(
    const float* __restrict__ X,  const float* __restrict__ L,
    const float* __restrict__ W1, const float* __restrict__ b1,
    const float* __restrict__ W2, const float* __restrict__ b2,
    const float* __restrict__ theta, float* __restrict__ out)
{
    extern __shared__ char dynsmem[];            // 32 KB: L-tile, later W1
    __half2* tile = reinterpret_cast<__half2*>(dynsmem);   // [64][128]
    float*   w1s  = reinterpret_cast<float*>(dynsmem);     // hf-phase alias

    __shared__ float sz[RPC], sr[RPC];
    __shared__ float4 redd[128];        // row-half-1 dot partials
    __shared__ float b1s[HID_];
    __shared__ float vsh[RPC];
    __shared__ float redh[8][16];       // hf warp partials
    __shared__ float hg[B_ * HID_];

    const int tid = threadIdx.x;
    const int bid = blockIdx.x;
    const int wtile = bid & 7;
    const int vchunk = bid >> 3;
    const int v0 = vchunk * RPC;

    // ---- Phase 0: convert MY 64x256 fp32 L tile into smem fp16 ----------
    {
        const float* Lsrc = L + (size_t)v0 * N_ + wtile * 256;
        for (int i = tid; i < 64 * 64; i += TPB) {     // 64 rows x 64 float4
            int row = i >> 6, q = i & 63;
            float4 f = reinterpret_cast<const float4*>(Lsrc + (size_t)row * N_)[q];
            tile[row * 128 + 2 * q]     = __floats2half2_rn(f.x, f.y);
            tile[row * 128 + 2 * q + 1] = __floats2half2_rn(f.z, f.w);
        }
    }
    __syncthreads();

    // ---- Passes 1..K: recon z/r for my chunk, partial dots from smem ----
    const int col = tid & 127;          // half2 column within tile
    const int rh  = tid >> 7;           // row half: 0 -> rows 0..31, 1 -> 32..63

    for (int j = 1; j <= K_; ++j) {
        const int pout = j & 1;
        const int pin  = pout ^ 1;

        if (j > 1) gsync(tid);          // partials of pass j-1 complete

        if (tid < 128) {                // recon on first 128 threads
            const int half = tid >> 6;  // 0: z, 1: r
            const int t = tid & 63;
            const int v = v0 + t;
            if (j == 1) {
                if (half == 0) sz[t] = 1.0f;                   // z_0
                else           sr[t] = theta[K_];              // r_0 = a_K
            } else if (half == 0) {
                float s = 0.f;
#pragma unroll
                for (int c = 0; c < VCHUNKS; ++c) s += g_pz[pin][c][v];
                float zold = (j == 2) ? 1.0f : g_zvec[pin][v];
                float znew = zold - s;
                sz[t] = znew;
                if (wtile == 0) g_zvec[pout][v] = znew;        // persist z_{j-1}
            } else {
                float s = 0.f, sp = 0.f;
#pragma unroll
                for (int c = 0; c < VCHUNKS; ++c) {
                    s  += g_pz[pin][c][v];
                    sp += g_pr[pin][c][v];
                }
                float zold = (j == 2) ? 1.0f : g_zvec[pin][v];
                float znew = zold - s;
                float aj = theta[K_ - j + 1] * c_binom[K_ - j + 1];
                sr[t] = sp + aj * znew;
            }
        }
        __syncthreads();

        float az0 = 0.f, az1 = 0.f, ar0 = 0.f, ar1 = 0.f;
        const int vb = rh * 32;
#pragma unroll
        for (int i = 0; i < 32; ++i) {
            const int vv = vb + i;
            float2 f = __half22float2(tile[vv * 128 + col]);
            float zc = sz[vv], rc = sr[vv];
            az0 += f.x * zc;  az1 += f.y * zc;
            ar0 += f.x * rc;  ar1 += f.y * rc;
        }
        if (rh == 1) redd[col] = make_float4(az0, az1, ar0, ar1);
        __syncthreads();
        if (rh == 0) {
            float4 o = redd[col];
            const int w2 = wtile * 128 + col;
            reinterpret_cast<float2*>(g_pz[pout][vchunk])[w2] =
                make_float2(az0 + o.x, az1 + o.y);
            reinterpret_cast<float2*>(g_pr[pout][vchunk])[w2] =
                make_float2(ar0 + o.z, ar1 + o.w);
        }
        __syncthreads();
    }

    gsync(tid);                          // pass-K partials complete (parity 0)

    // ---- hf phase: remap blocks, reconstruct v, GEMM + weighted reduce --
    {
        const int chunk = bid & 31;
        const int b = bid >> 5;
        const int tx = tid & 63;         // row within chunk
        const int ty = tid >> 6;         // 0..3 -> 16 hid each

        if (ty == 0) {                   // v[n] for my 64-row chunk
            int n = chunk * 64 + tx;
            float s = 0.f, sp = 0.f;
#pragma unroll
            for (int c = 0; c < VCHUNKS; ++c) {
                s  += g_pz[0][c][n];
                sp += g_pr[0][c][n];
            }
            float znew = g_zvec[0][n] - s;
            vsh[tx] = sp + theta[0] * znew;       // a_0 = theta_0
        }
        __syncthreads();                 // tile dead -> safe to overwrite

        for (int i = tid; i < F0_ * HID_; i += TPB) w1s[i] = W1[i];
        if (tid < HID_) b1s[tid] = b1[tid];
        __syncthreads();

        const int n = chunk * 64 + tx;
        const float* xr = X + ((size_t)b * N_ + n) * F0_;
        const int h0 = ty * 16;

        float acc[16];
#pragma unroll
        for (int h = 0; h < 16; ++h) acc[h] = b1s[h0 + h];

        for (int f0 = 0; f0 < F0_; f0 += 16) {
            float4 xv[4];
#pragma unroll
            for (int i = 0; i < 4; ++i)
                xv[i] = reinterpret_cast<const float4*>(xr + f0)[i];
            const float* xf = reinterpret_cast<const float*>(xv);
#pragma unroll
            for (int i = 0; i < 16; ++i) {
                float x = xf[i];
                const float4* wrow =
                    reinterpret_cast<const float4*>(&w1s[(f0 + i) * HID_ + h0]);
#pragma unroll
                for (int q = 0; q < 4; ++q) {
                    float4 wv = wrow[q];
                    acc[q * 4 + 0] += x * wv.x;
                    acc[q * 4 + 1] += x * wv.y;
                    acc[q * 4 + 2] += x * wv.z;
                    acc[q * 4 + 3] += x * wv.w;
                }
            }
        }

        float s = vsh[tx] * (1.0f / (float)N_);
#pragma unroll
        for (int h = 0; h < 16; ++h) acc[h] = fmaxf(acc[h], 0.f) * s;

        // warp shuffle over 32 rows, then pair warps via shared
#pragma unroll
        for (int h = 0; h < 16; ++h) {
            float v_ = acc[h];
            v_ += __shfl_xor_sync(0xffffffffu, v_, 16);
            v_ += __shfl_xor_sync(0xffffffffu, v_, 8);
            v_ += __shfl_xor_sync(0xffffffffu, v_, 4);
            v_ += __shfl_xor_sync(0xffffffffu, v_, 2);
            v_ += __shfl_xor_sync(0xffffffffu, v_, 1);
            acc[h] = v_;
        }
        int lane = tid & 31, warp = tid >> 5;     // warps 2g,2g+1 share ty=g
        if (lane == 0) {
#pragma unroll
            for (int h = 0; h < 16; ++h) redh[warp][h] = acc[h];
        }
        __syncthreads();
        if (tid < 64) {
            int g = tid >> 4, hh = tid & 15;
            g_part[b][chunk][g * 16 + hh] = redh[2 * g][hh] + redh[2 * g + 1][hh];
        }
    }

    gsync(tid);                          // all g_part written

    // ---- final: block 0 reduces chunks, logits = Hg@W2 + b2 ------------
    if (bid == 0) {
        for (int i = tid; i < B_ * HID_; i += TPB) {
            int bb = i >> 6, hh = i & 63;
            float s = 0.f;
#pragma unroll
            for (int c = 0; c < 32; ++c) s += g_part[bb][c][hh];
            hg[i] = s;
        }
        __syncthreads();
        if (tid < B_ * OUT_) {           // 128 threads = 8 batches x 16 outputs
            int bb = tid >> 4, o = tid & 15;
            float acc = b2[o];
#pragma unroll
            for (int hh = 0; hh < HID_; ++hh)
                acc += hg[bb * HID_ + hh] * W2[hh * OUT_ + o];
            out[bb * OUT_ + o] = acc;
        }
    }
}

// ---------------- launcher ----------------------------------------------
extern "C" void kernel_launch(void* const* d_in, const int* in_sizes, int n_in,
                              void* d_out, int out_size) {
    const float* X     = (const float*)d_in[0];
    const float* L     = (const float*)d_in[1];
    const float* W1    = (const float*)d_in[2];
    const float* b1    = (const float*)d_in[3];
    const float* W2    = (const float*)d_in[4];
    const float* b2    = (const float*)d_in[5];
    const float* theta = (const float*)d_in[6];
    float* out = (float*)d_out;

    mega_kernel<<<GRID, TPB, 32 * 1024>>>(X, L, W1, b1, W2, b2, theta, out);
}